// round 1
// baseline (speedup 1.0000x reference)
#include <cuda_runtime.h>
#include <math.h>

#define Bb 4
#define Ss 1024
#define Hh 1024
#define NHh 16
#define Dd 64
#define Pp 1024  /* 2*span */

__device__ __constant__ float INV_SCALE = 0.07216878364870322f; /* 1/sqrt(192) */

/* ------------------------- scratch ------------------------- */
__device__ float g_Q[(size_t)Bb * NHh * Ss * Dd];
__device__ float g_K[(size_t)Bb * NHh * Ss * Dd];
__device__ float g_V[(size_t)Bb * NHh * Ss * Dd];
__device__ float g_PK[(size_t)NHh * Pp * Dd];
__device__ float g_PQ[(size_t)NHh * Pp * Dd];
__device__ float g_C2P[(size_t)Bb * NHh * Ss * Pp];  /* [bh][q][p] = qhat . poskey[p] */
__device__ float g_P2C[(size_t)Bb * NHh * Ss * Pp];  /* [bh][k][p] = k . posqhat[p]  */
__device__ float g_CTX[(size_t)Bb * Ss * Hh];
__device__ float g_Y[(size_t)Bb * Ss * Hh];

/* ---------------- shared fp32 GEMM core (64x64x16, 256 thr, 4x4/thr) ---------------- */
template <bool TB>
__device__ __forceinline__ void gemm_core(const float* __restrict__ A, int lda,
                                          const float* __restrict__ Bm, int ldb,
                                          int m0, int n0, int K, float acc[4][4]) {
    __shared__ float As[16][64];
    __shared__ float Bs[16][64];
    int tid = threadIdx.x;
    int ty = tid >> 4, tx = tid & 15;
    for (int k0 = 0; k0 < K; k0 += 16) {
        {
            int r = tid >> 2, cq = (tid & 3) << 2;
            float4 v = *(const float4*)(A + (size_t)(m0 + r) * lda + k0 + cq);
            As[cq + 0][r] = v.x; As[cq + 1][r] = v.y;
            As[cq + 2][r] = v.z; As[cq + 3][r] = v.w;
            if (TB) {
                float4 w = *(const float4*)(Bm + (size_t)(n0 + r) * ldb + k0 + cq);
                Bs[cq + 0][r] = w.x; Bs[cq + 1][r] = w.y;
                Bs[cq + 2][r] = w.z; Bs[cq + 3][r] = w.w;
            } else {
                int rb = tid >> 4, cb = (tid & 15) << 2;
                *(float4*)&Bs[rb][cb] =
                    *(const float4*)(Bm + (size_t)(k0 + rb) * ldb + n0 + cb);
            }
        }
        __syncthreads();
#pragma unroll
        for (int kk = 0; kk < 16; kk++) {
            float4 av = *(const float4*)&As[kk][ty << 2];
            float4 bv = *(const float4*)&Bs[kk][tx << 2];
            float a[4] = {av.x, av.y, av.z, av.w};
            float b[4] = {bv.x, bv.y, bv.z, bv.w};
#pragma unroll
            for (int i = 0; i < 4; i++)
#pragma unroll
                for (int j = 0; j < 4; j++) acc[i][j] += a[i] * b[j];
        }
        __syncthreads();
    }
}

/* ---------------- kernel 1: QKV projection + bias + q-scale + head scatter ---------------- */
__global__ void __launch_bounds__(256) k_qkv(const float* __restrict__ A,
                                             const float* __restrict__ W,
                                             const float* __restrict__ qb,
                                             const float* __restrict__ vb) {
    float acc[4][4] = {};
    int n0 = blockIdx.x << 6, m0 = blockIdx.y << 6;
    gemm_core<false>(A, Hh, W, 3 * Hh, m0, n0, Hh, acc);
    int tid = threadIdx.x, ty = tid >> 4, tx = tid & 15;
    int n = n0 + (tx << 2);
    int h = n / 192;
    int rem = n - h * 192;
    int t = rem >> 6, d = rem & 63;
#pragma unroll
    for (int i = 0; i < 4; i++) {
        int m = m0 + (ty << 2) + i;
        int bb = m >> 10, s = m & 1023;
        size_t idx = (((size_t)bb * NHh + h) * Ss + s) * Dd + d;
        float4 r;
        if (t == 0) {
            float4 q4 = *(const float4*)(qb + h * 64 + d);
            r.x = (acc[i][0] + q4.x) * INV_SCALE;
            r.y = (acc[i][1] + q4.y) * INV_SCALE;
            r.z = (acc[i][2] + q4.z) * INV_SCALE;
            r.w = (acc[i][3] + q4.w) * INV_SCALE;
            *(float4*)&g_Q[idx] = r;
        } else if (t == 1) {
            r = make_float4(acc[i][0], acc[i][1], acc[i][2], acc[i][3]);
            *(float4*)&g_K[idx] = r;
        } else {
            float4 v4 = *(const float4*)(vb + h * 64 + d);
            r.x = acc[i][0] + v4.x; r.y = acc[i][1] + v4.y;
            r.z = acc[i][2] + v4.z; r.w = acc[i][3] + v4.w;
            *(float4*)&g_V[idx] = r;
        }
    }
}

/* ---------------- kernel 2: positional projections ---------------- */
__global__ void __launch_bounds__(256) k_pos(const float* __restrict__ RE,
                                             const float* __restrict__ W,
                                             const float* __restrict__ bias, int mode) {
    float acc[4][4] = {};
    int n0 = blockIdx.x << 6, m0 = blockIdx.y << 6;
    gemm_core<false>(RE, Hh, W, Hh, m0, n0, Hh, acc);
    int tid = threadIdx.x, ty = tid >> 4, tx = tid & 15;
    int n = n0 + (tx << 2);
    int h = n >> 6, d = n & 63;
#pragma unroll
    for (int i = 0; i < 4; i++) {
        int p = m0 + (ty << 2) + i;
        size_t idx = ((size_t)h * Pp + p) * Dd + d;
        if (mode == 0) {
            *(float4*)&g_PK[idx] =
                make_float4(acc[i][0], acc[i][1], acc[i][2], acc[i][3]);
        } else {
            float4 b4 = *(const float4*)(bias + n);
            float4 r;
            r.x = (acc[i][0] + b4.x) * INV_SCALE;
            r.y = (acc[i][1] + b4.y) * INV_SCALE;
            r.z = (acc[i][2] + b4.z) * INV_SCALE;
            r.w = (acc[i][3] + b4.w) * INV_SCALE;
            *(float4*)&g_PQ[idx] = r;
        }
    }
}

/* ---------------- kernel 3: batched NT GEMMs for c2p / p2c ---------------- */
__global__ void __launch_bounds__(256) k_rel(int mode) {
    int bh = blockIdx.z;
    int h = bh & (NHh - 1);
    const float* A = (mode == 0 ? g_Q : g_K) + (size_t)bh * Ss * Dd;
    const float* Bm = (mode == 0 ? g_PK : g_PQ) + (size_t)h * Pp * Dd;
    float* C = (mode == 0 ? g_C2P : g_P2C) + (size_t)bh * Ss * Pp;
    float acc[4][4] = {};
    int n0 = blockIdx.x << 6, m0 = blockIdx.y << 6;
    gemm_core<true>(A, Dd, Bm, Dd, m0, n0, Dd, acc);
    int tid = threadIdx.x, ty = tid >> 4, tx = tid & 15;
#pragma unroll
    for (int i = 0; i < 4; i++) {
        size_t off = (size_t)(m0 + (ty << 2) + i) * Pp + n0 + (tx << 2);
        *(float4*)&C[off] = make_float4(acc[i][0], acc[i][1], acc[i][2], acc[i][3]);
    }
}

/* ---------------- helpers for 16-lane row reductions ---------------- */
__device__ __forceinline__ float rowmax16(float v) {
#pragma unroll
    for (int o = 8; o; o >>= 1) v = fmaxf(v, __shfl_xor_sync(0xffffffffu, v, o, 16));
    return v;
}
__device__ __forceinline__ float rowsum16(float v) {
#pragma unroll
    for (int o = 8; o; o >>= 1) v += __shfl_xor_sync(0xffffffffu, v, o, 16);
    return v;
}

/* ---------------- kernel 4: fused attention (flash-style, 64x64 tiles) ---------------- */
__global__ void __launch_bounds__(256) k_attn() {
    extern __shared__ float sm[];
    float* Qts = sm;           /* [d][q]  64*64 */
    float* Kts = Qts + 4096;   /* [d][k]  64*64 */
    float* Vs  = Kts + 4096;   /* [k][d]  64*64 */
    float* Ps  = Vs + 4096;    /* [q][k]  64*64 */
    float* C2s = Ps + 4096;    /* [q][jb] 64*128 */
    float* P2s = C2s + 8192;   /* [k][jb] 64*128 */

    int q0 = blockIdx.x << 6;
    int bh = blockIdx.y;
    int b = bh >> 4, h = bh & 15;
    int tid = threadIdx.x, ty = tid >> 4, tx = tid & 15;

    const float* Qg = g_Q + (size_t)bh * Ss * Dd;
    const float* Kg = g_K + (size_t)bh * Ss * Dd;
    const float* Vg = g_V + (size_t)bh * Ss * Dd;
    const float* C2g = g_C2P + (size_t)bh * Ss * Pp;
    const float* P2g = g_P2C + (size_t)bh * Ss * Pp;

    /* load Q tile transposed: Qts[d][q] */
#pragma unroll
    for (int l = 0; l < 4; l++) {
        int idx = (l << 8) + tid;
        int r = idx >> 4, cq = (idx & 15) << 2;
        float4 v = *(const float4*)(Qg + (size_t)(q0 + r) * Dd + cq);
        Qts[(cq + 0) * 64 + r] = v.x; Qts[(cq + 1) * 64 + r] = v.y;
        Qts[(cq + 2) * 64 + r] = v.z; Qts[(cq + 3) * 64 + r] = v.w;
    }

    float O[4][4] = {};
    float mrow[4], lrow[4];
#pragma unroll
    for (int i = 0; i < 4; i++) { mrow[i] = -1e30f; lrow[i] = 0.f; }

    for (int kt = 0; kt < 16; kt++) {
        int k0 = kt << 6;
        __syncthreads();  /* previous PV read done (and Q load on first iter) */

        /* K tile transposed */
#pragma unroll
        for (int l = 0; l < 4; l++) {
            int idx = (l << 8) + tid;
            int r = idx >> 4, cq = (idx & 15) << 2;
            float4 v = *(const float4*)(Kg + (size_t)(k0 + r) * Dd + cq);
            Kts[(cq + 0) * 64 + r] = v.x; Kts[(cq + 1) * 64 + r] = v.y;
            Kts[(cq + 2) * 64 + r] = v.z; Kts[(cq + 3) * 64 + r] = v.w;
        }
        /* V tile natural */
#pragma unroll
        for (int l = 0; l < 4; l++) {
            int idx = (l << 8) + tid;
            int r = idx >> 4, c4 = (idx & 15) << 2;
            *(float4*)&Vs[r * 64 + c4] = *(const float4*)(Vg + (size_t)(k0 + r) * Dd + c4);
        }
        /* rel-pos bands: p = q - k + 512, band base */
        int pbase = q0 - k0 + 512 - 63;
#pragma unroll
        for (int l = 0; l < 32; l++) {
            int idx = (l << 8) + tid;
            int r = idx >> 7, j = idx & 127;
            int pc = min(max(pbase + j, 0), 1023);
            C2s[r * 128 + j] = C2g[(size_t)(q0 + r) * Pp + pc];
            P2s[r * 128 + j] = P2g[(size_t)(k0 + r) * Pp + pc];
        }
        __syncthreads();

        /* scores: Q . K^T */
        float sv[4][4] = {};
#pragma unroll 16
        for (int d = 0; d < 64; d++) {
            float4 av = *(const float4*)&Qts[d * 64 + (ty << 2)];
            float4 bv = *(const float4*)&Kts[d * 64 + (tx << 2)];
            float a[4] = {av.x, av.y, av.z, av.w};
            float bq[4] = {bv.x, bv.y, bv.z, bv.w};
#pragma unroll
            for (int i = 0; i < 4; i++)
#pragma unroll
                for (int j = 0; j < 4; j++) sv[i][j] += a[i] * bq[j];
        }
        /* add rel-pos gathers (same band index for both) */
#pragma unroll
        for (int i = 0; i < 4; i++)
#pragma unroll
            for (int j = 0; j < 4; j++) {
                int jb = ((ty << 2) + i) - ((tx << 2) + j) + 63;
                sv[i][j] += C2s[((ty << 2) + i) * 128 + jb] +
                            P2s[((tx << 2) + j) * 128 + jb];
            }
        /* online softmax */
#pragma unroll
        for (int i = 0; i < 4; i++) {
            float mx = fmaxf(fmaxf(sv[i][0], sv[i][1]), fmaxf(sv[i][2], sv[i][3]));
            mx = rowmax16(mx);
            float mn = fmaxf(mrow[i], mx);
            float alpha = __expf(mrow[i] - mn);
            float rs = 0.f;
#pragma unroll
            for (int j = 0; j < 4; j++) {
                float p = __expf(sv[i][j] - mn);
                sv[i][j] = p;
                rs += p;
            }
            rs = rowsum16(rs);
            lrow[i] = lrow[i] * alpha + rs;
            mrow[i] = mn;
#pragma unroll
            for (int j = 0; j < 4; j++) O[i][j] *= alpha;
            *(float4*)&Ps[((ty << 2) + i) * 64 + (tx << 2)] =
                make_float4(sv[i][0], sv[i][1], sv[i][2], sv[i][3]);
        }
        __syncthreads();
        /* PV accumulate */
#pragma unroll 16
        for (int kk = 0; kk < 64; kk++) {
            float4 bv = *(const float4*)&Vs[kk * 64 + (tx << 2)];
            float a0 = Ps[((ty << 2) + 0) * 64 + kk];
            float a1 = Ps[((ty << 2) + 1) * 64 + kk];
            float a2 = Ps[((ty << 2) + 2) * 64 + kk];
            float a3 = Ps[((ty << 2) + 3) * 64 + kk];
            O[0][0] += a0 * bv.x; O[0][1] += a0 * bv.y; O[0][2] += a0 * bv.z; O[0][3] += a0 * bv.w;
            O[1][0] += a1 * bv.x; O[1][1] += a1 * bv.y; O[1][2] += a1 * bv.z; O[1][3] += a1 * bv.w;
            O[2][0] += a2 * bv.x; O[2][1] += a2 * bv.y; O[2][2] += a2 * bv.z; O[2][3] += a2 * bv.w;
            O[3][0] += a3 * bv.x; O[3][1] += a3 * bv.y; O[3][2] += a3 * bv.z; O[3][3] += a3 * bv.w;
        }
    }
    /* epilogue: normalize, write ctx in (b, s, h*64+d) layout */
#pragma unroll
    for (int i = 0; i < 4; i++) {
        float inv = 1.0f / lrow[i];
        size_t off = ((size_t)b * Ss + q0 + (ty << 2) + i) * Hh + h * 64 + (tx << 2);
        *(float4*)&g_CTX[off] =
            make_float4(O[i][0] * inv, O[i][1] * inv, O[i][2] * inv, O[i][3] * inv);
    }
}

/* ---------------- kernel 5: output projection + bias + residual ---------------- */
__global__ void __launch_bounds__(256) k_out(const float* __restrict__ W,
                                             const float* __restrict__ bias,
                                             const float* __restrict__ hs) {
    float acc[4][4] = {};
    int n0 = blockIdx.x << 6, m0 = blockIdx.y << 6;
    gemm_core<false>(g_CTX, Hh, W, Hh, m0, n0, Hh, acc);
    int tid = threadIdx.x, ty = tid >> 4, tx = tid & 15;
    int n = n0 + (tx << 2);
    float4 b4 = *(const float4*)(bias + n);
#pragma unroll
    for (int i = 0; i < 4; i++) {
        int m = m0 + (ty << 2) + i;
        float4 h4 = *(const float4*)(hs + (size_t)m * Hh + n);
        *(float4*)&g_Y[(size_t)m * Hh + n] =
            make_float4(acc[i][0] + b4.x + h4.x, acc[i][1] + b4.y + h4.y,
                        acc[i][2] + b4.z + h4.z, acc[i][3] + b4.w + h4.w);
    }
}

/* ---------------- kernel 6: LayerNorm ---------------- */
__global__ void __launch_bounds__(256) k_ln(const float* __restrict__ gam,
                                            const float* __restrict__ bet,
                                            float* __restrict__ out) {
    int m = blockIdx.x;
    int tid = threadIdx.x;
    const float* y = g_Y + (size_t)m * Hh;
    float4 v = *(const float4*)(y + (tid << 2));
    float s = v.x + v.y + v.z + v.w;
    float s2 = v.x * v.x + v.y * v.y + v.z * v.z + v.w * v.w;
#pragma unroll
    for (int o = 16; o; o >>= 1) {
        s += __shfl_xor_sync(0xffffffffu, s, o);
        s2 += __shfl_xor_sync(0xffffffffu, s2, o);
    }
    __shared__ float sh[8], sh2[8];
    int w = tid >> 5, ln = tid & 31;
    if (ln == 0) { sh[w] = s; sh2[w] = s2; }
    __syncthreads();
    s = 0.f; s2 = 0.f;
#pragma unroll
    for (int i = 0; i < 8; i++) { s += sh[i]; s2 += sh2[i]; }
    float mean = s * (1.0f / Hh);
    float var = s2 * (1.0f / Hh) - mean * mean;
    float inv = rsqrtf(var + 1e-7f);
    float4 g4 = *(const float4*)(gam + (tid << 2));
    float4 b4 = *(const float4*)(bet + (tid << 2));
    float4 o4;
    o4.x = g4.x * (v.x - mean) * inv + b4.x;
    o4.y = g4.y * (v.y - mean) * inv + b4.y;
    o4.z = g4.z * (v.z - mean) * inv + b4.z;
    o4.w = g4.w * (v.w - mean) * inv + b4.w;
    *(float4*)(out + (size_t)m * Hh + (tid << 2)) = o4;
}

/* ---------------- launch ---------------- */
extern "C" void kernel_launch(void* const* d_in, const int* in_sizes, int n_in,
                              void* d_out, int out_size) {
    const float* hs   = (const float*)d_in[0];
    /* d_in[1] = attention_mask (all ones) — unused */
    const float* re   = (const float*)d_in[2];
    const float* w_in = (const float*)d_in[3];
    const float* qb   = (const float*)d_in[4];
    const float* vb   = (const float*)d_in[5];
    const float* w_pk = (const float*)d_in[6];
    const float* w_pq = (const float*)d_in[7];
    const float* b_pq = (const float*)d_in[8];
    const float* w_o  = (const float*)d_in[9];
    const float* b_o  = (const float*)d_in[10];
    const float* lng  = (const float*)d_in[11];
    const float* lnb  = (const float*)d_in[12];
    float* out = (float*)d_out;

    static int smem_set = 0;
    if (!smem_set) {
        cudaFuncSetAttribute(k_attn, cudaFuncAttributeMaxDynamicSharedMemorySize,
                             131072);
        smem_set = 1;
    }

    k_qkv<<<dim3(48, 64), 256>>>(hs, w_in, qb, vb);
    k_pos<<<dim3(16, 16), 256>>>(re, w_pk, nullptr, 0);
    k_pos<<<dim3(16, 16), 256>>>(re, w_pq, b_pq, 1);
    k_rel<<<dim3(16, 16, 64), 256>>>(0); /* c2p = Qhat x PK^T */
    k_rel<<<dim3(16, 16, 64), 256>>>(1); /* p2c = K x PQhat^T */
    k_attn<<<dim3(16, 64), 256, 131072>>>();
    k_out<<<dim3(16, 64), 256>>>(w_o, b_o, hs);
    k_ln<<<4096, 256>>>(lng, lnb, out);
}

// round 2
// speedup vs baseline: 1.8489x; 1.8489x over previous
#include <cuda_runtime.h>
#include <math.h>
#include <stdint.h>

#define Bb 4
#define Ss 1024
#define Hh 1024
#define NHh 16
#define Dd 64
#define Pp 1024

__device__ __constant__ float INV_SCALE_C = 0.07216878364870322f;
#define INV_SCALE 0.07216878364870322f

/* ------------------------- scratch ------------------------- */
__device__ float g_Q[(size_t)Bb * NHh * Ss * Dd];
__device__ float g_K[(size_t)Bb * NHh * Ss * Dd];
__device__ float g_V[(size_t)Bb * NHh * Ss * Dd];
__device__ float g_PK[(size_t)NHh * Pp * Dd];
__device__ float g_PQ[(size_t)NHh * Pp * Dd];
__device__ float g_C2P[(size_t)Bb * NHh * Ss * Pp];
__device__ float g_P2C[(size_t)Bb * NHh * Ss * Pp];
__device__ float g_CTX[(size_t)Bb * Ss * Hh];
__device__ float g_Y[(size_t)Bb * Ss * Hh];
__device__ float g_HS[(size_t)Bb * Ss * Hh];     /* tf32-rounded hidden */
__device__ float g_RE[(size_t)Pp * Hh];          /* tf32-rounded rel emb */
__device__ float g_WINT[(size_t)3 * Hh * Hh];    /* in_proj_w^T  [3072][1024] */
__device__ float g_WPKT[(size_t)Hh * Hh];
__device__ float g_WPQT[(size_t)Hh * Hh];
__device__ float g_WOT[(size_t)Hh * Hh];

/* ------------------------- tf32 helpers ------------------------- */
__device__ __forceinline__ float tf32r(float x) {
    uint32_t u;
    asm("cvt.rna.tf32.f32 %0, %1;" : "=r"(u) : "f"(x));
    return __uint_as_float(u);
}
__device__ __forceinline__ void cp16(uint32_t dst, const void* src) {
    asm volatile("cp.async.cg.shared.global [%0], [%1], 16;" :: "r"(dst), "l"(src));
}
__device__ __forceinline__ void cp_commit() { asm volatile("cp.async.commit_group;"); }
template <int N> __device__ __forceinline__ void cp_wait() {
    asm volatile("cp.async.wait_group %0;" :: "n"(N));
}
__device__ __forceinline__ void ldsm4(uint32_t a[4], uint32_t addr) {
    asm volatile("ldmatrix.sync.aligned.m8n8.x4.shared.b16 {%0,%1,%2,%3}, [%4];"
                 : "=r"(a[0]), "=r"(a[1]), "=r"(a[2]), "=r"(a[3]) : "r"(addr));
}
__device__ __forceinline__ void ldsm2(uint32_t b[2], uint32_t addr) {
    asm volatile("ldmatrix.sync.aligned.m8n8.x2.shared.b16 {%0,%1}, [%2];"
                 : "=r"(b[0]), "=r"(b[1]) : "r"(addr));
}
__device__ __forceinline__ void mma8(float c[4], const uint32_t a[4], const uint32_t b[2]) {
    asm volatile(
        "mma.sync.aligned.m16n8k8.row.col.f32.tf32.tf32.f32 "
        "{%0,%1,%2,%3}, {%4,%5,%6,%7}, {%8,%9}, {%0,%1,%2,%3};"
        : "+f"(c[0]), "+f"(c[1]), "+f"(c[2]), "+f"(c[3])
        : "r"(a[0]), "r"(a[1]), "r"(a[2]), "r"(a[3]), "r"(b[0]), "r"(b[1]));
}

/* ------------------------- prep kernels ------------------------- */
__global__ void __launch_bounds__(256) k_round(const float* __restrict__ src, int which) {
    float* dst = which == 0 ? g_HS : g_RE;
    size_t i = ((size_t)blockIdx.x * 256 + threadIdx.x) * 4;
    float4 v = *(const float4*)(src + i);
    v.x = tf32r(v.x); v.y = tf32r(v.y); v.z = tf32r(v.z); v.w = tf32r(v.w);
    *(float4*)(dst + i) = v;
}

/* src [K][N] -> dst [N][K], rounded to tf32 */
__global__ void __launch_bounds__(256) k_transp(const float* __restrict__ src, int which,
                                                int K, int N) {
    float* dst = which == 0 ? g_WINT : which == 1 ? g_WPKT : which == 2 ? g_WPQT : g_WOT;
    __shared__ float s[32][33];
    int n0 = blockIdx.x << 5, k0 = blockIdx.y << 5;
    int tx = threadIdx.x, ty = threadIdx.y;
#pragma unroll
    for (int j = 0; j < 4; j++)
        s[ty + j * 8][tx] = src[(size_t)(k0 + ty + j * 8) * N + n0 + tx];
    __syncthreads();
#pragma unroll
    for (int j = 0; j < 4; j++)
        dst[(size_t)(n0 + ty + j * 8) * K + k0 + tx] = tf32r(s[tx][ty + j * 8]);
}

/* ------------------------- unified tf32 GEMM -------------------------
 * Block tile 128(M) x 256(N), K-stage 32, 8 warps, warp tile 64x64.
 * MODE 0: qkv   A=g_HS   B=g_WINT          K=1024, epilogue scatter Q/K/V
 * MODE 1: pos   A=g_RE   B=g_WPKT/g_WPQT   K=1024, z selects pk/pq
 * MODE 3: rel   A=g_Q/g_K B=g_PK/g_PQ      K=64,   z in [0,128): c2p / p2c
 * MODE 4: out   A=g_CTX  B=g_WOT           K=1024, +bias+residual -> g_Y
 */
#define STAGE_B 49152u  /* (128+256)*32*4 */

template <int MODE>
__global__ void __launch_bounds__(256, 1) gemm_k(const float* __restrict__ x1,
                                                 const float* __restrict__ x2) {
    constexpr int KDIM = (MODE == 3) ? 64 : 1024;
    constexpr int NS = KDIM / 32;

    const float* A;
    const float* B;
    float* C = nullptr;
    int lda, ldb;
    int z = blockIdx.z;
    if (MODE == 0) { A = g_HS; B = g_WINT; lda = 1024; ldb = 1024; }
    else if (MODE == 1) { A = g_RE; B = (z ? g_WPQT : g_WPKT); lda = 1024; ldb = 1024; }
    else if (MODE == 3) {
        int zz = z & 63;
        A = (z < 64 ? g_Q : g_K) + (size_t)zz * Ss * Dd;
        B = (z < 64 ? g_PK : g_PQ) + (size_t)(zz & 15) * Pp * Dd;
        C = (z < 64 ? g_C2P : g_P2C) + (size_t)zz * Ss * Pp;
        lda = 64; ldb = 64;
    } else { A = g_CTX; B = g_WOT; lda = 1024; ldb = 1024; }

    extern __shared__ float smem[];
    uint32_t sbase = (uint32_t)__cvta_generic_to_shared(smem);

    int tid = threadIdx.x;
    int lane = tid & 31, wid = tid >> 5;
    int wm = wid & 1, wn = wid >> 1;
    int m0 = blockIdx.y << 7, n0 = blockIdx.x << 8;

    int kcopy = tid & 7, rsub = tid >> 3;
    const float* asrc0 = A + (size_t)(m0 + rsub) * lda + kcopy * 4;
    const float* bsrc0 = B + (size_t)(n0 + rsub) * ldb + kcopy * 4;

    float c[4][8][4];
#pragma unroll
    for (int i = 0; i < 4; i++)
#pragma unroll
        for (int j = 0; j < 8; j++)
#pragma unroll
            for (int r = 0; r < 4; r++) c[i][j][r] = 0.f;

    /* stage copy lambda-free macro */
#define STAGE_COPY(slot, kofs)                                                       \
    {                                                                                \
        uint32_t sb = sbase + (slot) * STAGE_B;                                      \
        _Pragma("unroll") for (int it = 0; it < 4; it++) {                           \
            int row = it * 32 + rsub;                                                \
            uint32_t d = sb + (((row << 3) + (kcopy ^ (row & 7))) << 4);             \
            cp16(d, asrc0 + (size_t)it * 32 * lda + (kofs));                         \
        }                                                                            \
        _Pragma("unroll") for (int it = 0; it < 8; it++) {                           \
            int row = it * 32 + rsub;                                                \
            uint32_t d = sb + 16384u + (((row << 3) + (kcopy ^ (row & 7))) << 4);    \
            cp16(d, bsrc0 + (size_t)it * 32 * ldb + (kofs));                         \
        }                                                                            \
        cp_commit();                                                                 \
    }

    STAGE_COPY(0, 0)

    int arow_l = wm * 64 + (lane & 15);
    int akhalf = lane >> 4;
    int brow_base = wn * 64 + (lane & 7);
    int bkhalf = (lane >> 3) & 1;

    for (int s = 0; s < NS; s++) {
        if (s + 1 < NS) { STAGE_COPY((s + 1) & 1, (s + 1) * 32) cp_wait<1>(); }
        else cp_wait<0>();
        __syncthreads();

        uint32_t sA = sbase + (s & 1) * STAGE_B;
        uint32_t sB = sA + 16384u;

#pragma unroll
        for (int kc = 0; kc < 4; kc++) {
            uint32_t bf[8][2];
#pragma unroll
            for (int nst = 0; nst < 8; nst++) {
                int row = brow_base + nst * 8;
                int col = kc * 2 + bkhalf;
                ldsm2(bf[nst], sB + (((row << 3) + (col ^ (row & 7))) << 4));
            }
#pragma unroll
            for (int st = 0; st < 4; st++) {
                uint32_t af[4];
                int row = arow_l + st * 16;
                int col = kc * 2 + akhalf;
                ldsm4(af, sA + (((row << 3) + (col ^ (row & 7))) << 4));
#pragma unroll
                for (int nst = 0; nst < 8; nst++) mma8(c[st][nst], af, bf[nst]);
            }
        }
        __syncthreads();
    }

    /* ---------------- epilogue ---------------- */
    int g = lane >> 2, q2 = lane & 3;
    int mbt = m0 + wm * 64, nbt = n0 + wn * 64;
#pragma unroll
    for (int st = 0; st < 4; st++) {
#pragma unroll
        for (int nst = 0; nst < 8; nst++) {
#pragma unroll
            for (int half = 0; half < 2; half++) {
                int m = mbt + st * 16 + g + half * 8;
                int n = nbt + nst * 8 + q2 * 2;
                float v0 = c[st][nst][half * 2 + 0];
                float v1 = c[st][nst][half * 2 + 1];
                if (MODE == 0) {
                    int h = n / 192, rem = n - h * 192;
                    int t = rem >> 6, d = rem & 63;
                    int bq = m >> 10, srow = m & 1023;
                    size_t idx = (((size_t)(bq * 16 + h)) * 1024 + srow) * 64 + d;
                    if (t == 0) {
                        g_Q[idx] = tf32r((v0 + x1[h * 64 + d]) * INV_SCALE);
                        g_Q[idx + 1] = tf32r((v1 + x1[h * 64 + d + 1]) * INV_SCALE);
                    } else if (t == 1) {
                        g_K[idx] = tf32r(v0);
                        g_K[idx + 1] = tf32r(v1);
                    } else {
                        g_V[idx] = v0 + x2[h * 64 + d];
                        g_V[idx + 1] = v1 + x2[h * 64 + d + 1];
                    }
                } else if (MODE == 1) {
                    int h = n >> 6, d = n & 63;
                    size_t idx = ((size_t)h * 1024 + m) * 64 + d;
                    if (z == 0) {
                        g_PK[idx] = tf32r(v0);
                        g_PK[idx + 1] = tf32r(v1);
                    } else {
                        g_PQ[idx] = tf32r((v0 + x1[n]) * INV_SCALE);
                        g_PQ[idx + 1] = tf32r((v1 + x1[n + 1]) * INV_SCALE);
                    }
                } else if (MODE == 3) {
                    *(float2*)&C[(size_t)m * 1024 + n] = make_float2(v0, v1);
                } else {
                    size_t o = (size_t)m * 1024 + n;
                    g_Y[o] = v0 + x1[n] + x2[o];
                    g_Y[o + 1] = v1 + x1[n + 1] + x2[o + 1];
                }
            }
        }
    }
#undef STAGE_COPY
}

/* ---------------- 16-lane row reductions ---------------- */
__device__ __forceinline__ float rowmax16(float v) {
#pragma unroll
    for (int o = 8; o; o >>= 1) v = fmaxf(v, __shfl_xor_sync(0xffffffffu, v, o, 16));
    return v;
}
__device__ __forceinline__ float rowsum16(float v) {
#pragma unroll
    for (int o = 8; o; o >>= 1) v += __shfl_xor_sync(0xffffffffu, v, o, 16);
    return v;
}

/* ---------------- fused attention (flash-style, 64x64 tiles) ---------------- */
__global__ void __launch_bounds__(256) k_attn() {
    extern __shared__ float sm[];
    float* Qts = sm;
    float* Kts = Qts + 4096;
    float* Vs  = Kts + 4096;
    float* Ps  = Vs + 4096;
    float* C2s = Ps + 4096;
    float* P2s = C2s + 8192;

    int q0 = blockIdx.x << 6;
    int bh = blockIdx.y;
    int b = bh >> 4, h = bh & 15;
    int tid = threadIdx.x, ty = tid >> 4, tx = tid & 15;

    const float* Qg = g_Q + (size_t)bh * Ss * Dd;
    const float* Kg = g_K + (size_t)bh * Ss * Dd;
    const float* Vg = g_V + (size_t)bh * Ss * Dd;
    const float* C2g = g_C2P + (size_t)bh * Ss * Pp;
    const float* P2g = g_P2C + (size_t)bh * Ss * Pp;

#pragma unroll
    for (int l = 0; l < 4; l++) {
        int idx = (l << 8) + tid;
        int r = idx >> 4, cq = (idx & 15) << 2;
        float4 v = *(const float4*)(Qg + (size_t)(q0 + r) * Dd + cq);
        Qts[(cq + 0) * 64 + r] = v.x; Qts[(cq + 1) * 64 + r] = v.y;
        Qts[(cq + 2) * 64 + r] = v.z; Qts[(cq + 3) * 64 + r] = v.w;
    }

    float O[4][4] = {};
    float mrow[4], lrow[4];
#pragma unroll
    for (int i = 0; i < 4; i++) { mrow[i] = -1e30f; lrow[i] = 0.f; }

    for (int kt = 0; kt < 16; kt++) {
        int k0 = kt << 6;
        __syncthreads();
#pragma unroll
        for (int l = 0; l < 4; l++) {
            int idx = (l << 8) + tid;
            int r = idx >> 4, cq = (idx & 15) << 2;
            float4 v = *(const float4*)(Kg + (size_t)(k0 + r) * Dd + cq);
            Kts[(cq + 0) * 64 + r] = v.x; Kts[(cq + 1) * 64 + r] = v.y;
            Kts[(cq + 2) * 64 + r] = v.z; Kts[(cq + 3) * 64 + r] = v.w;
        }
#pragma unroll
        for (int l = 0; l < 4; l++) {
            int idx = (l << 8) + tid;
            int r = idx >> 4, c4 = (idx & 15) << 2;
            *(float4*)&Vs[r * 64 + c4] = *(const float4*)(Vg + (size_t)(k0 + r) * Dd + c4);
        }
        int pbase = q0 - k0 + 512 - 63;
#pragma unroll
        for (int l = 0; l < 32; l++) {
            int idx = (l << 8) + tid;
            int r = idx >> 7, j = idx & 127;
            int pc = min(max(pbase + j, 0), 1023);
            C2s[r * 128 + j] = C2g[(size_t)(q0 + r) * Pp + pc];
            P2s[r * 128 + j] = P2g[(size_t)(k0 + r) * Pp + pc];
        }
        __syncthreads();

        float sv[4][4] = {};
#pragma unroll 16
        for (int d = 0; d < 64; d++) {
            float4 av = *(const float4*)&Qts[d * 64 + (ty << 2)];
            float4 bv = *(const float4*)&Kts[d * 64 + (tx << 2)];
            float a[4] = {av.x, av.y, av.z, av.w};
            float bq[4] = {bv.x, bv.y, bv.z, bv.w};
#pragma unroll
            for (int i = 0; i < 4; i++)
#pragma unroll
                for (int j = 0; j < 4; j++) sv[i][j] += a[i] * bq[j];
        }
#pragma unroll
        for (int i = 0; i < 4; i++)
#pragma unroll
            for (int j = 0; j < 4; j++) {
                int jb = ((ty << 2) + i) - ((tx << 2) + j) + 63;
                sv[i][j] += C2s[((ty << 2) + i) * 128 + jb] +
                            P2s[((tx << 2) + j) * 128 + jb];
            }
#pragma unroll
        for (int i = 0; i < 4; i++) {
            float mx = fmaxf(fmaxf(sv[i][0], sv[i][1]), fmaxf(sv[i][2], sv[i][3]));
            mx = rowmax16(mx);
            float mn = fmaxf(mrow[i], mx);
            float alpha = __expf(mrow[i] - mn);
            float rs = 0.f;
#pragma unroll
            for (int j = 0; j < 4; j++) {
                float p = __expf(sv[i][j] - mn);
                sv[i][j] = p;
                rs += p;
            }
            rs = rowsum16(rs);
            lrow[i] = lrow[i] * alpha + rs;
            mrow[i] = mn;
#pragma unroll
            for (int j = 0; j < 4; j++) O[i][j] *= alpha;
            *(float4*)&Ps[((ty << 2) + i) * 64 + (tx << 2)] =
                make_float4(sv[i][0], sv[i][1], sv[i][2], sv[i][3]);
        }
        __syncthreads();
#pragma unroll 16
        for (int kk = 0; kk < 64; kk++) {
            float4 bv = *(const float4*)&Vs[kk * 64 + (tx << 2)];
            float a0 = Ps[((ty << 2) + 0) * 64 + kk];
            float a1 = Ps[((ty << 2) + 1) * 64 + kk];
            float a2 = Ps[((ty << 2) + 2) * 64 + kk];
            float a3 = Ps[((ty << 2) + 3) * 64 + kk];
            O[0][0] += a0 * bv.x; O[0][1] += a0 * bv.y; O[0][2] += a0 * bv.z; O[0][3] += a0 * bv.w;
            O[1][0] += a1 * bv.x; O[1][1] += a1 * bv.y; O[1][2] += a1 * bv.z; O[1][3] += a1 * bv.w;
            O[2][0] += a2 * bv.x; O[2][1] += a2 * bv.y; O[2][2] += a2 * bv.z; O[2][3] += a2 * bv.w;
            O[3][0] += a3 * bv.x; O[3][1] += a3 * bv.y; O[3][2] += a3 * bv.z; O[3][3] += a3 * bv.w;
        }
    }
#pragma unroll
    for (int i = 0; i < 4; i++) {
        float inv = 1.0f / lrow[i];
        size_t off = ((size_t)b * Ss + q0 + (ty << 2) + i) * Hh + h * 64 + (tx << 2);
        *(float4*)&g_CTX[off] =
            make_float4(tf32r(O[i][0] * inv), tf32r(O[i][1] * inv),
                        tf32r(O[i][2] * inv), tf32r(O[i][3] * inv));
    }
}

/* ---------------- LayerNorm ---------------- */
__global__ void __launch_bounds__(256) k_ln(const float* __restrict__ gam,
                                            const float* __restrict__ bet,
                                            float* __restrict__ out) {
    int m = blockIdx.x;
    int tid = threadIdx.x;
    const float* y = g_Y + (size_t)m * Hh;
    float4 v = *(const float4*)(y + (tid << 2));
    float s = v.x + v.y + v.z + v.w;
    float s2 = v.x * v.x + v.y * v.y + v.z * v.z + v.w * v.w;
#pragma unroll
    for (int o = 16; o; o >>= 1) {
        s += __shfl_xor_sync(0xffffffffu, s, o);
        s2 += __shfl_xor_sync(0xffffffffu, s2, o);
    }
    __shared__ float sh[8], sh2[8];
    int w = tid >> 5, ln = tid & 31;
    if (ln == 0) { sh[w] = s; sh2[w] = s2; }
    __syncthreads();
    s = 0.f; s2 = 0.f;
#pragma unroll
    for (int i = 0; i < 8; i++) { s += sh[i]; s2 += sh2[i]; }
    float mean = s * (1.0f / Hh);
    float var = s2 * (1.0f / Hh) - mean * mean;
    float inv = rsqrtf(var + 1e-7f);
    float4 g4 = *(const float4*)(gam + (tid << 2));
    float4 b4 = *(const float4*)(bet + (tid << 2));
    float4 o4;
    o4.x = g4.x * (v.x - mean) * inv + b4.x;
    o4.y = g4.y * (v.y - mean) * inv + b4.y;
    o4.z = g4.z * (v.z - mean) * inv + b4.z;
    o4.w = g4.w * (v.w - mean) * inv + b4.w;
    *(float4*)(out + (size_t)m * Hh + (tid << 2)) = o4;
}

/* ---------------- launch ---------------- */
extern "C" void kernel_launch(void* const* d_in, const int* in_sizes, int n_in,
                              void* d_out, int out_size) {
    const float* hs   = (const float*)d_in[0];
    const float* re   = (const float*)d_in[2];
    const float* w_in = (const float*)d_in[3];
    const float* qb   = (const float*)d_in[4];
    const float* vb   = (const float*)d_in[5];
    const float* w_pk = (const float*)d_in[6];
    const float* w_pq = (const float*)d_in[7];
    const float* b_pq = (const float*)d_in[8];
    const float* w_o  = (const float*)d_in[9];
    const float* b_o  = (const float*)d_in[10];
    const float* lng  = (const float*)d_in[11];
    const float* lnb  = (const float*)d_in[12];
    float* out = (float*)d_out;

    static int attr_set = 0;
    if (!attr_set) {
        cudaFuncSetAttribute(k_attn, cudaFuncAttributeMaxDynamicSharedMemorySize, 131072);
        cudaFuncSetAttribute(gemm_k<0>, cudaFuncAttributeMaxDynamicSharedMemorySize, 98304);
        cudaFuncSetAttribute(gemm_k<1>, cudaFuncAttributeMaxDynamicSharedMemorySize, 98304);
        cudaFuncSetAttribute(gemm_k<3>, cudaFuncAttributeMaxDynamicSharedMemorySize, 98304);
        cudaFuncSetAttribute(gemm_k<4>, cudaFuncAttributeMaxDynamicSharedMemorySize, 98304);
        attr_set = 1;
    }

    /* prep: round A-operands, transpose+round weights */
    k_round<<<4096, 256>>>(hs, 0);                       /* 4M floats */
    k_round<<<1024, 256>>>(re, 1);                       /* 1M floats */
    k_transp<<<dim3(96, 32), dim3(32, 8)>>>(w_in, 0, 1024, 3072);
    k_transp<<<dim3(32, 32), dim3(32, 8)>>>(w_pk, 1, 1024, 1024);
    k_transp<<<dim3(32, 32), dim3(32, 8)>>>(w_pq, 2, 1024, 1024);
    k_transp<<<dim3(32, 32), dim3(32, 8)>>>(w_o, 3, 1024, 1024);

    gemm_k<0><<<dim3(12, 32), 256, 98304>>>(qb, vb);
    gemm_k<1><<<dim3(4, 8, 2), 256, 98304>>>(b_pq, nullptr);
    gemm_k<3><<<dim3(4, 8, 128), 256, 98304>>>(nullptr, nullptr);
    k_attn<<<dim3(16, 64), 256, 131072>>>();
    gemm_k<4><<<dim3(4, 32), 256, 98304>>>(b_o, hs);
    k_ln<<<4096, 256>>>(lng, lnb, out);
}

// round 3
// speedup vs baseline: 3.3437x; 1.8084x over previous
#include <cuda_runtime.h>
#include <math.h>
#include <stdint.h>

#define Bb 4
#define Ss 1024
#define Hh 1024
#define NHh 16
#define Dd 64
#define Pp 1024

#define INV_SCALE 0.07216878364870322f

/* ------------------------- scratch ------------------------- */
__device__ float g_Q[(size_t)Bb * NHh * Ss * Dd];
__device__ float g_K[(size_t)Bb * NHh * Ss * Dd];
__device__ float g_VT[(size_t)Bb * NHh * Dd * Ss];   /* [bh][d][s] */
__device__ float g_PK[(size_t)NHh * Pp * Dd];
__device__ float g_PQ[(size_t)NHh * Pp * Dd];
__device__ float g_CTX[(size_t)Bb * Ss * Hh];
__device__ float g_Y[(size_t)Bb * Ss * Hh];
__device__ float g_HS[(size_t)Bb * Ss * Hh];
__device__ float g_RE[(size_t)Pp * Hh];
__device__ float g_WINT[(size_t)3 * Hh * Hh];
__device__ float g_WPKT[(size_t)Hh * Hh];
__device__ float g_WPQT[(size_t)Hh * Hh];
__device__ float g_WOT[(size_t)Hh * Hh];

/* ------------------------- helpers ------------------------- */
__device__ __forceinline__ float tf32r(float x) {
    uint32_t u;
    asm("cvt.rna.tf32.f32 %0, %1;" : "=r"(u) : "f"(x));
    return __uint_as_float(u);
}
__device__ __forceinline__ void cp16(uint32_t dst, const void* src) {
    asm volatile("cp.async.cg.shared.global [%0], [%1], 16;" :: "r"(dst), "l"(src));
}
__device__ __forceinline__ void cp_commit() { asm volatile("cp.async.commit_group;"); }
template <int N> __device__ __forceinline__ void cp_wait() {
    asm volatile("cp.async.wait_group %0;" :: "n"(N));
}
__device__ __forceinline__ void ldsm4(uint32_t a[4], uint32_t addr) {
    asm volatile("ldmatrix.sync.aligned.m8n8.x4.shared.b16 {%0,%1,%2,%3}, [%4];"
                 : "=r"(a[0]), "=r"(a[1]), "=r"(a[2]), "=r"(a[3]) : "r"(addr));
}
__device__ __forceinline__ void ldsm2(uint32_t b[2], uint32_t addr) {
    asm volatile("ldmatrix.sync.aligned.m8n8.x2.shared.b16 {%0,%1}, [%2];"
                 : "=r"(b[0]), "=r"(b[1]) : "r"(addr));
}
__device__ __forceinline__ void mma8(float c[4], const uint32_t a[4], const uint32_t b[2]) {
    asm volatile(
        "mma.sync.aligned.m16n8k8.row.col.f32.tf32.tf32.f32 "
        "{%0,%1,%2,%3}, {%4,%5,%6,%7}, {%8,%9}, {%0,%1,%2,%3};"
        : "+f"(c[0]), "+f"(c[1]), "+f"(c[2]), "+f"(c[3])
        : "r"(a[0]), "r"(a[1]), "r"(a[2]), "r"(a[3]), "r"(b[0]), "r"(b[1]));
}

/* swizzled 64-col tile addressing: 16 chunks of 16B per row */
#define SW_OFF(row, c) ((((row) << 4) + (((c) & 8) | (((c) & 7) ^ ((row) & 7)))) << 4)

/* ------------------------- prep kernels ------------------------- */
__global__ void __launch_bounds__(256) k_round(const float* __restrict__ src, int which) {
    float* dst = which == 0 ? g_HS : g_RE;
    size_t i = ((size_t)blockIdx.x * 256 + threadIdx.x) * 4;
    float4 v = *(const float4*)(src + i);
    v.x = tf32r(v.x); v.y = tf32r(v.y); v.z = tf32r(v.z); v.w = tf32r(v.w);
    *(float4*)(dst + i) = v;
}

__global__ void __launch_bounds__(256) k_transp(const float* __restrict__ src, int which,
                                                int K, int N) {
    float* dst = which == 0 ? g_WINT : which == 1 ? g_WPKT : which == 2 ? g_WPQT : g_WOT;
    __shared__ float s[32][33];
    int n0 = blockIdx.x << 5, k0 = blockIdx.y << 5;
    int tx = threadIdx.x, ty = threadIdx.y;
#pragma unroll
    for (int j = 0; j < 4; j++)
        s[ty + j * 8][tx] = src[(size_t)(k0 + ty + j * 8) * N + n0 + tx];
    __syncthreads();
#pragma unroll
    for (int j = 0; j < 4; j++)
        dst[(size_t)(n0 + ty + j * 8) * K + k0 + tx] = tf32r(s[tx][ty + j * 8]);
}

/* ------------------------- tf32 GEMM (modes 0,1,4) ------------------------- */
#define STAGE_B 49152u

template <int MODE>
__global__ void __launch_bounds__(256, 1) gemm_k(const float* __restrict__ x1,
                                                 const float* __restrict__ x2) {
    constexpr int NS = 32;
    const float* A;
    const float* B;
    int z = blockIdx.z;
    if (MODE == 0) { A = g_HS; B = g_WINT; }
    else if (MODE == 1) { A = g_RE; B = (z ? g_WPQT : g_WPKT); }
    else { A = g_CTX; B = g_WOT; }
    const int lda = 1024, ldb = 1024;

    extern __shared__ float smem[];
    uint32_t sbase = (uint32_t)__cvta_generic_to_shared(smem);

    int tid = threadIdx.x;
    int lane = tid & 31, wid = tid >> 5;
    int wm = wid & 1, wn = wid >> 1;
    int m0 = blockIdx.y << 7, n0 = blockIdx.x << 8;

    int kcopy = tid & 7, rsub = tid >> 3;
    const float* asrc0 = A + (size_t)(m0 + rsub) * lda + kcopy * 4;
    const float* bsrc0 = B + (size_t)(n0 + rsub) * ldb + kcopy * 4;

    float c[4][8][4];
#pragma unroll
    for (int i = 0; i < 4; i++)
#pragma unroll
        for (int j = 0; j < 8; j++)
#pragma unroll
            for (int r = 0; r < 4; r++) c[i][j][r] = 0.f;

#define STAGE_COPY(slot, kofs)                                                       \
    {                                                                                \
        uint32_t sb = sbase + (slot) * STAGE_B;                                      \
        _Pragma("unroll") for (int it = 0; it < 4; it++) {                           \
            int row = it * 32 + rsub;                                                \
            uint32_t d = sb + (((row << 3) + (kcopy ^ (row & 7))) << 4);             \
            cp16(d, asrc0 + (size_t)it * 32 * lda + (kofs));                         \
        }                                                                            \
        _Pragma("unroll") for (int it = 0; it < 8; it++) {                           \
            int row = it * 32 + rsub;                                                \
            uint32_t d = sb + 16384u + (((row << 3) + (kcopy ^ (row & 7))) << 4);    \
            cp16(d, bsrc0 + (size_t)it * 32 * ldb + (kofs));                         \
        }                                                                            \
        cp_commit();                                                                 \
    }

    STAGE_COPY(0, 0)

    int arow_l = wm * 64 + (lane & 15);
    int akhalf = lane >> 4;
    int brow_base = wn * 64 + (lane & 7);
    int bkhalf = (lane >> 3) & 1;

    for (int s = 0; s < NS; s++) {
        if (s + 1 < NS) { STAGE_COPY((s + 1) & 1, (s + 1) * 32) cp_wait<1>(); }
        else cp_wait<0>();
        __syncthreads();

        uint32_t sA = sbase + (s & 1) * STAGE_B;
        uint32_t sB = sA + 16384u;

#pragma unroll
        for (int kc = 0; kc < 4; kc++) {
            uint32_t bf[8][2];
#pragma unroll
            for (int nst = 0; nst < 8; nst++) {
                int row = brow_base + nst * 8;
                int col = kc * 2 + bkhalf;
                ldsm2(bf[nst], sB + (((row << 3) + (col ^ (row & 7))) << 4));
            }
#pragma unroll
            for (int st = 0; st < 4; st++) {
                uint32_t af[4];
                int row = arow_l + st * 16;
                int col = kc * 2 + akhalf;
                ldsm4(af, sA + (((row << 3) + (col ^ (row & 7))) << 4));
#pragma unroll
                for (int nst = 0; nst < 8; nst++) mma8(c[st][nst], af, bf[nst]);
            }
        }
        __syncthreads();
    }

    int g = lane >> 2, q2 = lane & 3;
    int mbt = m0 + wm * 64, nbt = n0 + wn * 64;
#pragma unroll
    for (int st = 0; st < 4; st++) {
#pragma unroll
        for (int nst = 0; nst < 8; nst++) {
#pragma unroll
            for (int half = 0; half < 2; half++) {
                int m = mbt + st * 16 + g + half * 8;
                int n = nbt + nst * 8 + q2 * 2;
                float v0 = c[st][nst][half * 2 + 0];
                float v1 = c[st][nst][half * 2 + 1];
                if (MODE == 0) {
                    int h = n / 192, rem = n - h * 192;
                    int t = rem >> 6, d = rem & 63;
                    int bq = m >> 10, srow = m & 1023;
                    size_t idx = (((size_t)(bq * 16 + h)) * 1024 + srow) * 64 + d;
                    if (t == 0) {
                        g_Q[idx] = tf32r((v0 + x1[h * 64 + d]) * INV_SCALE);
                        g_Q[idx + 1] = tf32r((v1 + x1[h * 64 + d + 1]) * INV_SCALE);
                    } else if (t == 1) {
                        g_K[idx] = tf32r(v0);
                        g_K[idx + 1] = tf32r(v1);
                    } else {
                        size_t vt = (((size_t)(bq * 16 + h)) * 64 + d) * 1024 + srow;
                        g_VT[vt] = tf32r(v0 + x2[h * 64 + d]);
                        g_VT[vt + 1024] = tf32r(v1 + x2[h * 64 + d + 1]);
                    }
                } else if (MODE == 1) {
                    int h = n >> 6, d = n & 63;
                    size_t idx = ((size_t)h * 1024 + m) * 64 + d;
                    if (z == 0) {
                        g_PK[idx] = tf32r(v0);
                        g_PK[idx + 1] = tf32r(v1);
                    } else {
                        g_PQ[idx] = tf32r((v0 + x1[n]) * INV_SCALE);
                        g_PQ[idx + 1] = tf32r((v1 + x1[n + 1]) * INV_SCALE);
                    }
                } else {
                    size_t o = (size_t)m * 1024 + n;
                    g_Y[o] = v0 + x1[n] + x2[o];
                    g_Y[o + 1] = v1 + x1[n + 1] + x2[o + 1];
                }
            }
        }
    }
#undef STAGE_COPY
}

/* ---------------- fused attention: QK + c2p + p2c bands + softmax + PV, all tf32 mma ----------------
 * 128 threads, 4 warps; block = 64 q rows of one (b,h).
 * SMEM floats: Qs@0(4096) Ks@4096(4096) Vt@8192(4096) Ps@12288(4096)
 *              B1@16384(8448): PK band (swizzled) aliased with C2 (64x132 linear)
 *              B2@24832(8448): PQ band aliased with P2.  Total 33280 f = 133120 B.
 */
#define TW 132

__global__ void __launch_bounds__(128, 1) k_attn2() {
    extern __shared__ float sm[];
    uint32_t sb = (uint32_t)__cvta_generic_to_shared(sm);
    const uint32_t uQ = sb;
    const uint32_t uK = sb + 4096u * 4u;
    const uint32_t uV = sb + 8192u * 4u;
    const uint32_t uP = sb + 12288u * 4u;
    const uint32_t uB1 = sb + 16384u * 4u;
    const uint32_t uB2 = sb + 24832u * 4u;
    float* C2 = sm + 16384;
    float* P2 = sm + 24832;

    int tid = threadIdx.x, lane = tid & 31, wid = tid >> 5;
    int q0 = blockIdx.x << 6, bh = blockIdx.y;
    int b = bh >> 4, h = bh & 15;
    const float* Qg = g_Q + (size_t)bh * 65536;
    const float* Kg = g_K + (size_t)bh * 65536;
    const float* Vg = g_VT + (size_t)bh * 65536;
    const float* PKg = g_PK + (size_t)h * 65536;
    const float* PQg = g_PQ + (size_t)h * 65536;

    int lc = tid & 15, lr = tid >> 4;
    int g = lane >> 2, q2 = lane & 3;
    int wq0 = wid << 4;

    /* Q tile (persistent) */
#pragma unroll
    for (int i = 0; i < 4; i++) {
        int r = lr + 8 * i;
        cp16(uQ + SW_OFF(r, lc), Qg + (size_t)(q0 + r) * 64 + lc * 4);
        int r2 = r + 32;
        cp16(uQ + SW_OFF(r2, lc), Qg + (size_t)(q0 + r2) * 64 + lc * 4);
    }

    float O[8][4];
#pragma unroll
    for (int i = 0; i < 8; i++)
#pragma unroll
        for (int j = 0; j < 4; j++) O[i][j] = 0.f;
    float mA = -1e30f, mB = -1e30f, lA = 0.f, lB = 0.f;

    for (int kt = 0; kt < 16; kt++) {
        int k0 = kt << 6;
        __syncthreads();

        /* ---- stage loads ---- */
#pragma unroll
        for (int i = 0; i < 8; i++) {
            int r = lr + 8 * i;
            cp16(uK + SW_OFF(r, lc), Kg + (size_t)(k0 + r) * 64 + lc * 4);
        }
#pragma unroll
        for (int i = 0; i < 8; i++) {
            int r = lr + 8 * i;
            cp16(uV + SW_OFF(r, lc), Vg + (size_t)r * 1024 + k0 + lc * 4);
        }
        int pb1 = q0 - k0 + 449, pb2 = k0 - q0 + 449;
#pragma unroll
        for (int i = 0; i < 16; i++) {
            int r = lr + 8 * i;
            int pr = min(max(pb1 + r, 0), 1023);
            cp16(uB1 + SW_OFF(r, lc), PKg + (size_t)pr * 64 + lc * 4);
        }
#pragma unroll
        for (int i = 0; i < 16; i++) {
            int r = lr + 8 * i;
            int pr = min(max(pb2 + r, 0), 1023);
            cp16(uB2 + SW_OFF(r, lc), PQg + (size_t)pr * 64 + lc * 4);
        }
        cp_commit();
        cp_wait<0>();
        __syncthreads();

        /* ---- c2p band mma: C2band[q (warp rows)][128 j] ---- */
        {
            float acc[16][4];
#pragma unroll
            for (int i = 0; i < 16; i++)
#pragma unroll
                for (int j = 0; j < 4; j++) acc[i][j] = 0.f;
#pragma unroll
            for (int ks = 0; ks < 8; ks++) {
                uint32_t a[4];
                ldsm4(a, uQ + SW_OFF(wq0 + (lane & 15), ks * 2 + (lane >> 4)));
#pragma unroll
                for (int np = 0; np < 8; np++) {
                    uint32_t bq[4];
                    int srow = np * 16 + (((lane >> 4) & 1) << 3) + (lane & 7);
                    int sc = ks * 2 + ((lane >> 3) & 1);
                    ldsm4(bq, uB1 + SW_OFF(srow, sc));
                    mma8(acc[np * 2], a, bq);
                    mma8(acc[np * 2 + 1], a, bq + 2);
                }
            }
            __syncthreads(); /* all warps done reading PK band */
#pragma unroll
            for (int f = 0; f < 16; f++) {
                int col = f * 8 + q2 * 2;
                *(float2*)&C2[(wq0 + g) * TW + col] = make_float2(acc[f][0], acc[f][1]);
                *(float2*)&C2[(wq0 + g + 8) * TW + col] = make_float2(acc[f][2], acc[f][3]);
            }
        }

        float sS[8][4];
#pragma unroll
        for (int i = 0; i < 8; i++)
#pragma unroll
            for (int j = 0; j < 4; j++) sS[i][j] = 0.f;

        /* ---- p2c band + QK mma ---- */
        {
            float acc[16][4];
#pragma unroll
            for (int i = 0; i < 16; i++)
#pragma unroll
                for (int j = 0; j < 4; j++) acc[i][j] = 0.f;
#pragma unroll
            for (int ks = 0; ks < 8; ks++) {
                uint32_t a[4];
                ldsm4(a, uK + SW_OFF(wq0 + (lane & 15), ks * 2 + (lane >> 4)));
#pragma unroll
                for (int np = 0; np < 8; np++) {
                    uint32_t bq[4];
                    int srow = np * 16 + (((lane >> 4) & 1) << 3) + (lane & 7);
                    int sc = ks * 2 + ((lane >> 3) & 1);
                    ldsm4(bq, uB2 + SW_OFF(srow, sc));
                    mma8(acc[np * 2], a, bq);
                    mma8(acc[np * 2 + 1], a, bq + 2);
                }
            }
            /* QK */
#pragma unroll
            for (int ks = 0; ks < 8; ks++) {
                uint32_t a[4];
                ldsm4(a, uQ + SW_OFF(wq0 + (lane & 15), ks * 2 + (lane >> 4)));
#pragma unroll
                for (int np = 0; np < 4; np++) {
                    uint32_t bq[4];
                    int srow = np * 16 + (((lane >> 4) & 1) << 3) + (lane & 7);
                    int sc = ks * 2 + ((lane >> 3) & 1);
                    ldsm4(bq, uK + SW_OFF(srow, sc));
                    mma8(sS[np * 2], a, bq);
                    mma8(sS[np * 2 + 1], a, bq + 2);
                }
            }
            __syncthreads(); /* all warps done reading PQ band */
#pragma unroll
            for (int f = 0; f < 16; f++) {
                int col = f * 8 + q2 * 2;
                *(float2*)&P2[(wq0 + g) * TW + col] = make_float2(acc[f][0], acc[f][1]);
                *(float2*)&P2[(wq0 + g + 8) * TW + col] = make_float2(acc[f][2], acc[f][3]);
            }
        }
        __syncthreads(); /* band results visible */

        /* ---- fixup + online softmax ---- */
        int qiA = wq0 + g, qiB = qiA + 8;
#pragma unroll
        for (int nst = 0; nst < 8; nst++) {
            int kj = nst * 8 + q2 * 2;
            sS[nst][0] += C2[qiA * TW + 63 + qiA - kj] + P2[kj * TW + 63 + kj - qiA];
            sS[nst][1] += C2[qiA * TW + 62 + qiA - kj] + P2[(kj + 1) * TW + 64 + kj - qiA];
            sS[nst][2] += C2[qiB * TW + 63 + qiB - kj] + P2[kj * TW + 63 + kj - qiB];
            sS[nst][3] += C2[qiB * TW + 62 + qiB - kj] + P2[(kj + 1) * TW + 64 + kj - qiB];
        }
        float mxA = -1e30f, mxB = -1e30f;
#pragma unroll
        for (int nst = 0; nst < 8; nst++) {
            mxA = fmaxf(mxA, fmaxf(sS[nst][0], sS[nst][1]));
            mxB = fmaxf(mxB, fmaxf(sS[nst][2], sS[nst][3]));
        }
        mxA = fmaxf(mxA, __shfl_xor_sync(0xffffffffu, mxA, 1, 4));
        mxA = fmaxf(mxA, __shfl_xor_sync(0xffffffffu, mxA, 2, 4));
        mxB = fmaxf(mxB, __shfl_xor_sync(0xffffffffu, mxB, 1, 4));
        mxB = fmaxf(mxB, __shfl_xor_sync(0xffffffffu, mxB, 2, 4));
        float mnA = fmaxf(mA, mxA), mnB = fmaxf(mB, mxB);
        float aA = __expf(mA - mnA), aB = __expf(mB - mnB);
        float rsA = 0.f, rsB = 0.f;
#pragma unroll
        for (int nst = 0; nst < 8; nst++) {
            float p0 = tf32r(__expf(sS[nst][0] - mnA));
            float p1 = tf32r(__expf(sS[nst][1] - mnA));
            float p2v = tf32r(__expf(sS[nst][2] - mnB));
            float p3 = tf32r(__expf(sS[nst][3] - mnB));
            rsA += p0 + p1;
            rsB += p2v + p3;
            int col = nst * 8 + q2 * 2;
            int ch = col >> 2, wo = (col & 3) << 2;
            *(float2*)((char*)sm + 49152 + SW_OFF(qiA, ch) + wo) = make_float2(p0, p1);
            *(float2*)((char*)sm + 49152 + SW_OFF(qiB, ch) + wo) = make_float2(p2v, p3);
        }
        rsA += __shfl_xor_sync(0xffffffffu, rsA, 1, 4);
        rsA += __shfl_xor_sync(0xffffffffu, rsA, 2, 4);
        rsB += __shfl_xor_sync(0xffffffffu, rsB, 1, 4);
        rsB += __shfl_xor_sync(0xffffffffu, rsB, 2, 4);
        lA = lA * aA + rsA;
        lB = lB * aB + rsB;
        mA = mnA;
        mB = mnB;
#pragma unroll
        for (int i = 0; i < 8; i++) {
            O[i][0] *= aA; O[i][1] *= aA;
            O[i][2] *= aB; O[i][3] *= aB;
        }
        __syncwarp();

        /* ---- PV mma: O += P(own 16 q rows) @ V ---- */
#pragma unroll
        for (int ks = 0; ks < 8; ks++) {
            uint32_t a[4];
            ldsm4(a, uP + SW_OFF(wq0 + (lane & 15), ks * 2 + (lane >> 4)));
#pragma unroll
            for (int np = 0; np < 4; np++) {
                uint32_t bq[4];
                int srow = np * 16 + (((lane >> 4) & 1) << 3) + (lane & 7);
                int sc = ks * 2 + ((lane >> 3) & 1);
                ldsm4(bq, uV + SW_OFF(srow, sc));
                mma8(O[np * 2], a, bq);
                mma8(O[np * 2 + 1], a, bq + 2);
            }
        }
    }

    /* ---- epilogue ---- */
    float invA = 1.f / lA, invB = 1.f / lB;
    int qA = q0 + wq0 + g, qB = qA + 8;
#pragma unroll
    for (int np = 0; np < 8; np++) {
        int d0 = h * 64 + np * 8 + q2 * 2;
        *(float2*)&g_CTX[((size_t)(b * 1024) + qA) * 1024 + d0] =
            make_float2(tf32r(O[np][0] * invA), tf32r(O[np][1] * invA));
        *(float2*)&g_CTX[((size_t)(b * 1024) + qB) * 1024 + d0] =
            make_float2(tf32r(O[np][2] * invB), tf32r(O[np][3] * invB));
    }
}

/* ---------------- LayerNorm ---------------- */
__global__ void __launch_bounds__(256) k_ln(const float* __restrict__ gam,
                                            const float* __restrict__ bet,
                                            float* __restrict__ out) {
    int m = blockIdx.x;
    int tid = threadIdx.x;
    const float* y = g_Y + (size_t)m * Hh;
    float4 v = *(const float4*)(y + (tid << 2));
    float s = v.x + v.y + v.z + v.w;
    float s2 = v.x * v.x + v.y * v.y + v.z * v.z + v.w * v.w;
#pragma unroll
    for (int o = 16; o; o >>= 1) {
        s += __shfl_xor_sync(0xffffffffu, s, o);
        s2 += __shfl_xor_sync(0xffffffffu, s2, o);
    }
    __shared__ float sh[8], sh2[8];
    int w = tid >> 5, ln = tid & 31;
    if (ln == 0) { sh[w] = s; sh2[w] = s2; }
    __syncthreads();
    s = 0.f; s2 = 0.f;
#pragma unroll
    for (int i = 0; i < 8; i++) { s += sh[i]; s2 += sh2[i]; }
    float mean = s * (1.0f / Hh);
    float var = s2 * (1.0f / Hh) - mean * mean;
    float inv = rsqrtf(var + 1e-7f);
    float4 g4 = *(const float4*)(gam + (tid << 2));
    float4 b4 = *(const float4*)(bet + (tid << 2));
    float4 o4;
    o4.x = g4.x * (v.x - mean) * inv + b4.x;
    o4.y = g4.y * (v.y - mean) * inv + b4.y;
    o4.z = g4.z * (v.z - mean) * inv + b4.z;
    o4.w = g4.w * (v.w - mean) * inv + b4.w;
    *(float4*)(out + (size_t)m * Hh + (tid << 2)) = o4;
}

/* ---------------- launch ---------------- */
extern "C" void kernel_launch(void* const* d_in, const int* in_sizes, int n_in,
                              void* d_out, int out_size) {
    const float* hs   = (const float*)d_in[0];
    const float* re   = (const float*)d_in[2];
    const float* w_in = (const float*)d_in[3];
    const float* qb   = (const float*)d_in[4];
    const float* vb   = (const float*)d_in[5];
    const float* w_pk = (const float*)d_in[6];
    const float* w_pq = (const float*)d_in[7];
    const float* b_pq = (const float*)d_in[8];
    const float* w_o  = (const float*)d_in[9];
    const float* b_o  = (const float*)d_in[10];
    const float* lng  = (const float*)d_in[11];
    const float* lnb  = (const float*)d_in[12];
    float* out = (float*)d_out;

    static int attr_set = 0;
    if (!attr_set) {
        cudaFuncSetAttribute(k_attn2, cudaFuncAttributeMaxDynamicSharedMemorySize, 133120);
        cudaFuncSetAttribute(gemm_k<0>, cudaFuncAttributeMaxDynamicSharedMemorySize, 98304);
        cudaFuncSetAttribute(gemm_k<1>, cudaFuncAttributeMaxDynamicSharedMemorySize, 98304);
        cudaFuncSetAttribute(gemm_k<4>, cudaFuncAttributeMaxDynamicSharedMemorySize, 98304);
        attr_set = 1;
    }

    k_round<<<4096, 256>>>(hs, 0);
    k_round<<<1024, 256>>>(re, 1);
    k_transp<<<dim3(96, 32), dim3(32, 8)>>>(w_in, 0, 1024, 3072);
    k_transp<<<dim3(32, 32), dim3(32, 8)>>>(w_pk, 1, 1024, 1024);
    k_transp<<<dim3(32, 32), dim3(32, 8)>>>(w_pq, 2, 1024, 1024);
    k_transp<<<dim3(32, 32), dim3(32, 8)>>>(w_o, 3, 1024, 1024);

    gemm_k<0><<<dim3(12, 32), 256, 98304>>>(qb, vb);
    gemm_k<1><<<dim3(4, 8, 2), 256, 98304>>>(b_pq, nullptr);
    k_attn2<<<dim3(16, 64), 128, 133120>>>();
    gemm_k<4><<<dim3(4, 32), 256, 98304>>>(b_o, hs);
    k_ln<<<4096, 256>>>(lng, lnb, out);
}